// round 14
// baseline (speedup 1.0000x reference)
#include <cuda_runtime.h>
#include <cuda_fp16.h>
#include <cstdint>

// ---------------- problem constants ----------------
#define N_    16
#define CIN   512
#define COUT  512
#define HH    64
#define WW    64
#define SDIM  512
#define EPSF  1e-8f
#define MTOT  (N_ * 32 * 32)       // 16384 winograd tiles

// ---------------- GEMM tiling ----------------
#define TILE_M 128
#define TILE_N 128
#define KCH    32                  // ci per k-chunk
#define NITER  (CIN / KCH)         // 16
#define STAGES 3
#define ROWB   80                  // padded smem row stride (bytes) for 64B rows
#define ARR_B  (128 * ROWB)
#define STAGE_B (2 * ARR_B)
#define SMEM_TOTAL (STAGES * STAGE_B)   // 61440

#define VSTRIP 8                   // vtrans strip length (ty tiles per CTA)

// ---------------- device scratch ----------------
__device__ float g_s[N_ * CIN];
__device__ float g_wsq[COUT * CIN];
__device__ float g_dm[N_ * COUT];
__device__ __half g_U[(size_t)16 * COUT * CIN];     // weight transform, [xi][co][ci]
__device__ __half g_V[(size_t)16 * MTOT * CIN];     // input transform,  [xi][m][ci]
__device__ __half g_M[(size_t)16 * COUT * MTOT];    // GEMM result fp16, [xi][co][m]

// ---------------- PTX helpers ----------------
__device__ __forceinline__ uint32_t smem_u32(const void* p) {
    uint32_t a;
    asm("{ .reg .u64 t; cvta.to.shared.u64 t, %1; cvt.u32.u64 %0, t; }" : "=r"(a) : "l"(p));
    return a;
}
__device__ __forceinline__ void cp16(uint32_t dst, const void* src) {
    asm volatile("cp.async.cg.shared.global [%0], [%1], 16;" :: "r"(dst), "l"(src));
}
#define CP_COMMIT() asm volatile("cp.async.commit_group;" ::: "memory")
#define CP_WAIT2()  asm volatile("cp.async.wait_group 2;" ::: "memory")

__device__ __forceinline__ void ldm_x4(uint32_t r[4], uint32_t addr) {
    asm volatile("ldmatrix.sync.aligned.m8n8.x4.shared.b16 {%0,%1,%2,%3}, [%4];"
                 : "=r"(r[0]), "=r"(r[1]), "=r"(r[2]), "=r"(r[3]) : "r"(addr));
}
__device__ __forceinline__ void mma_f16(float c[4], const uint32_t a[4],
                                        uint32_t b0, uint32_t b1) {
    asm volatile(
        "mma.sync.aligned.m16n8k16.row.col.f32.f16.f16.f32 "
        "{%0,%1,%2,%3}, {%4,%5,%6,%7}, {%8,%9}, {%0,%1,%2,%3};"
        : "+f"(c[0]), "+f"(c[1]), "+f"(c[2]), "+f"(c[3])
        : "r"(a[0]), "r"(a[1]), "r"(a[2]), "r"(a[3]), "r"(b0), "r"(b1));
}
__device__ __forceinline__ float warp_sum(float v) {
#pragma unroll
    for (int o = 16; o > 0; o >>= 1)
        v += __shfl_xor_sync(0xFFFFFFFFu, v, o);
    return v;
}
__device__ __forceinline__ float4 f4add(float4 a, float4 b) {
    return make_float4(a.x + b.x, a.y + b.y, a.z + b.z, a.w + b.w);
}
__device__ __forceinline__ float4 f4sub(float4 a, float4 b) {
    return make_float4(a.x - b.x, a.y - b.y, a.z - b.z, a.w - b.w);
}

// ---------------------------------------------------------------------------
// U = G (w*ws) G^T  fp16 [xi][co][ci]; also wsq.  Coalesced via smem staging.
__global__ void k_wprep(const float* __restrict__ w) {
    __shared__ float wsm[CIN * 9];   // 18 KB
    const int co = blockIdx.x, t = threadIdx.x;
    const float4* src4 = (const float4*)(w + (size_t)co * CIN * 9);
#pragma unroll
    for (int i = t; i < CIN * 9 / 4; i += 256) ((float4*)wsm)[i] = src4[i];
    __syncthreads();
    const float ws = rsqrtf((float)(CIN * 9));
#pragma unroll
    for (int cq = 0; cq < 2; cq++) {
        int ci = cq * 256 + t;
        float g[9], acc = 0.f;
#pragma unroll
        for (int i = 0; i < 9; i++) { g[i] = wsm[ci * 9 + i]; acc += g[i] * g[i]; }
        g_wsq[co * CIN + ci] = acc;
#pragma unroll
        for (int i = 0; i < 9; i++) g[i] *= ws;
        float tG[4][3];
#pragma unroll
        for (int c = 0; c < 3; c++) {
            tG[0][c] = g[c];
            tG[1][c] = 0.5f * (g[c] + g[3 + c] + g[6 + c]);
            tG[2][c] = 0.5f * (g[c] - g[3 + c] + g[6 + c]);
            tG[3][c] = g[6 + c];
        }
#pragma unroll
        for (int r = 0; r < 4; r++) {
            float u0 = tG[r][0];
            float u1 = 0.5f * (tG[r][0] + tG[r][1] + tG[r][2]);
            float u2 = 0.5f * (tG[r][0] - tG[r][1] + tG[r][2]);
            float u3 = tG[r][2];
            g_U[((size_t)(r * 4 + 0) * COUT + co) * CIN + ci] = __float2half(u0);
            g_U[((size_t)(r * 4 + 1) * COUT + co) * CIN + ci] = __float2half(u1);
            g_U[((size_t)(r * 4 + 2) * COUT + co) * CIN + ci] = __float2half(u2);
            g_U[((size_t)(r * 4 + 3) * COUT + co) * CIN + ci] = __float2half(u3);
        }
    }
}

// ---------------------------------------------------------------------------
__global__ void k_style(const float* __restrict__ style,
                        const float* __restrict__ style_w,
                        const float* __restrict__ style_b) {
    __shared__ float sty[SDIM];
    const int n = blockIdx.x;
    const int t = threadIdx.x, lane = t & 31, wp = t >> 5;
    sty[t] = style[n * SDIM + t];
    sty[t + 256] = style[n * SDIM + t + 256];
    __syncthreads();
    const float lin_scale = rsqrtf((float)SDIM);
#pragma unroll
    for (int q = 0; q < 4; q++) {
        int c = blockIdx.y * 32 + wp * 4 + q;
        const float* wr = style_w + (size_t)c * SDIM;
        float acc = 0.f;
#pragma unroll
        for (int i = 0; i < SDIM / 32; i++)
            acc += sty[i * 32 + lane] * wr[i * 32 + lane];
        acc = warp_sum(acc);
        if (lane == 0) g_s[n * CIN + c] = acc * lin_scale + style_b[c];
    }
}

// ---------------------------------------------------------------------------
__global__ void k_demod() {
    __shared__ float s2[CIN];
    const int n = blockIdx.x;
    const int t = threadIdx.x, lane = t & 31, wp = t >> 5;
    float a0 = g_s[n * CIN + t], a1 = g_s[n * CIN + t + 256];
    s2[t] = a0 * a0;
    s2[t + 256] = a1 * a1;
    __syncthreads();
    const float ws = rsqrtf((float)(CIN * 9));
#pragma unroll
    for (int q = 0; q < 4; q++) {
        int o = blockIdx.y * 32 + wp * 4 + q;
        const float* wr = g_wsq + (size_t)o * CIN;
        float acc = 0.f;
#pragma unroll
        for (int i = 0; i < CIN / 32; i++)
            acc += s2[i * 32 + lane] * wr[i * 32 + lane];
        acc = warp_sum(acc);
        if (lane == 0) g_dm[n * COUT + o] = rsqrtf(ws * ws * acc + EPSF);
    }
}

// ---------------------------------------------------------------------------
// V = B^T (x*s) B  fp16 [xi][m][ci].  Register-carried row pairs: each ty
// re-uses d[2],d[3] from the previous iteration; only 2 new rows hit smem.
// grid = (16 cig, N_ n, 32/VSTRIP strips), block = 256
__global__ void __launch_bounds__(256, 2)
k_vtrans(const float* __restrict__ x) {
    __shared__ float srow[2][66][36];   // 2-row staging; 16B-aligned float4
    __shared__ float ssc[32];
    const int cig = blockIdx.x, n = blockIdx.y;
    const int ty0 = blockIdx.z * VSTRIP;
    const int t = threadIdx.x;

    if (t < 32) ssc[t] = g_s[n * CIN + cig * 32 + t];
    if (t < 128) {   // zero halo columns 0 and 65 in both slots
        int slot = (t >> 6) & 1, side = (t >> 5) & 1, ci = t & 31;
        srow[slot][side * 65][ci] = 0.f;
    }
    __syncthreads();   // ssc + halo visible before any scaled fill

    const float* xb = x + ((size_t)(n * CIN + cig * 32)) * HH * WW;

    // refill 2 rows ybase, ybase+1 into slots 0,1 (1024 float4 over 256 thr)
#define REFILL(ybase)                                                         \
    do {                                                                      \
        _Pragma("unroll")                                                     \
        for (int u = 0; u < 4; u++) {                                         \
            int id = u * 256 + t;                                             \
            int rr = id >> 9;                                                 \
            int rem = id & 511;                                               \
            int xq = rem & 15, ci = rem >> 4;                                 \
            int y = (ybase) + rr;                                             \
            float4 v = make_float4(0.f, 0.f, 0.f, 0.f);                       \
            if (y >= 0 && y < HH)                                             \
                v = *(const float4*)&xb[((size_t)ci * HH + y) * WW + xq * 4]; \
            float sc = ssc[ci];                                               \
            srow[rr][xq * 4 + 1][ci] = v.x * sc;                              \
            srow[rr][xq * 4 + 2][ci] = v.y * sc;                              \
            srow[rr][xq * 4 + 3][ci] = v.z * sc;                              \
            srow[rr][xq * 4 + 4][ci] = v.w * sc;                              \
        }                                                                     \
    } while (0)

    const int ttx = t >> 3;           // tile column 0..31
    const int tci = (t & 7) * 4;      // ci base within group

    float4 d[4][4];                   // [row][col], carried across ty

    // initial fill: rows 2ty0-1, 2ty0 -> d[0],d[1]; rows 2ty0+1, 2ty0+2 -> d[2],d[3]
    REFILL(2 * ty0 - 1);
    __syncthreads();
#pragma unroll
    for (int c = 0; c < 4; c++) {
        d[0][c] = *(const float4*)&srow[0][2 * ttx + c][tci];
        d[1][c] = *(const float4*)&srow[1][2 * ttx + c][tci];
    }
    __syncthreads();
    REFILL(2 * ty0 + 1);
    __syncthreads();
#pragma unroll
    for (int c = 0; c < 4; c++) {
        d[2][c] = *(const float4*)&srow[0][2 * ttx + c][tci];
        d[3][c] = *(const float4*)&srow[1][2 * ttx + c][tci];
    }

    for (int ty = ty0; ty < ty0 + VSTRIP; ty++) {
        // ---- transform from registers (identical op order to R12) ----
        float4 z[4][4];
#pragma unroll
        for (int c = 0; c < 4; c++) {
            z[0][c] = f4sub(d[0][c], d[2][c]);
            z[1][c] = f4add(d[1][c], d[2][c]);
            z[2][c] = f4sub(d[2][c], d[1][c]);
            z[3][c] = f4sub(d[1][c], d[3][c]);
        }
        size_t mb = ((size_t)(n * 1024 + ty * 32 + ttx)) * CIN + cig * 32 + tci;
#pragma unroll
        for (int i = 0; i < 4; i++) {
            float4 v[4];
            v[0] = f4sub(z[i][0], z[i][2]);
            v[1] = f4add(z[i][1], z[i][2]);
            v[2] = f4sub(z[i][2], z[i][1]);
            v[3] = f4sub(z[i][1], z[i][3]);
#pragma unroll
            for (int j = 0; j < 4; j++) {
                __half2 h0 = __floats2half2_rn(v[j].x, v[j].y);
                __half2 h1 = __floats2half2_rn(v[j].z, v[j].w);
                uint2 u = make_uint2(*(uint32_t*)&h0, *(uint32_t*)&h1);
                *(uint2*)&g_V[(size_t)(i * 4 + j) * (MTOT * CIN) + mb] = u;
            }
        }
        if (ty + 1 < ty0 + VSTRIP) {
            __syncthreads();              // prior d-loads done before overwrite
            REFILL(2 * ty + 3);           // rows 2ty+3, 2ty+4
            __syncthreads();              // STS visible
#pragma unroll
            for (int c = 0; c < 4; c++) { // carry + load new rows
                d[0][c] = d[2][c];
                d[1][c] = d[3][c];
                d[2][c] = *(const float4*)&srow[0][2 * ttx + c][tci];
                d[3][c] = *(const float4*)&srow[1][2 * ttx + c][tci];
            }
        }
    }
#undef REFILL
}

// ---------------------------------------------------------------------------
// Stage loader: A = V[xi][m0..+128][32ci], B = U[xi][co0..+128][32ci]
__device__ __forceinline__ void load_stage(uint32_t sbase, int xi, int m0, int co0,
                                           int cic, int t) {
#pragma unroll
    for (int u = 0; u < 2; u++) {
        int id = u * 256 + t;
        int row = id >> 2, seg = id & 3;
        const __half* src = g_V + ((size_t)xi * MTOT + m0 + row) * CIN + cic * KCH + seg * 8;
        cp16(sbase + row * ROWB + seg * 16, src);
    }
#pragma unroll
    for (int u = 0; u < 2; u++) {
        int id = u * 256 + t;
        int row = id >> 2, seg = id & 3;
        const __half* src = g_U + ((size_t)xi * COUT + co0 + row) * CIN + cic * KCH + seg * 8;
        cp16(sbase + ARR_B + row * ROWB + seg * 16, src);
    }
}

// ---------------------------------------------------------------------------
// Winograd-domain GEMM: M[xi][co][m] = V[xi][m][ci] * U[xi][co][ci], fp16 out.
__global__ void __launch_bounds__(256, 2)
k_gemm() {
    extern __shared__ __align__(16) char smem[];
    const uint32_t sb = smem_u32(smem);

    const int t = threadIdx.x;
    const int lane = t & 31;
    const int w = t >> 5;
    const int warp_m = w & 3;
    const int warp_n = w >> 2;
    const int m0 = blockIdx.x * TILE_M;
    const int co0 = blockIdx.y * TILE_N;
    const int xi = blockIdx.z;

    const uint32_t a_off =
        (uint32_t)((warp_m * 32 + (lane & 15)) * ROWB + (lane >> 4) * 16);
    const uint32_t b_off =
        (uint32_t)(ARR_B +
                   (warp_n * 64 + (lane & 7) + (lane >> 4) * 8) * ROWB +
                   ((lane >> 3) & 1) * 16);

    float acc[2][8][4];
#pragma unroll
    for (int mt = 0; mt < 2; mt++)
#pragma unroll
        for (int nt = 0; nt < 8; nt++)
#pragma unroll
            for (int q = 0; q < 4; q++) acc[mt][nt][q] = 0.f;

    load_stage(sb + 0 * STAGE_B, xi, m0, co0, 0, t);
    CP_COMMIT();
    load_stage(sb + 1 * STAGE_B, xi, m0, co0, 1, t);
    CP_COMMIT();

    int st = 0;
    for (int j = 0; j < NITER; j++) {
        if (j + 2 < NITER) {
            int s2 = (j + 2) % STAGES;
            load_stage(sb + s2 * STAGE_B, xi, m0, co0, j + 2, t);
        }
        CP_COMMIT();
        CP_WAIT2();
        __syncthreads();

        const uint32_t base = sb + st * STAGE_B;
#pragma unroll
        for (int ks = 0; ks < 2; ks++) {
            const uint32_t ko = ks * 32;
            uint32_t ah[2][4];
#pragma unroll
            for (int mt = 0; mt < 2; mt++)
                ldm_x4(ah[mt], base + a_off + mt * 16 * ROWB + ko);
            uint32_t bh[4][4];
#pragma unroll
            for (int p = 0; p < 4; p++)
                ldm_x4(bh[p], base + b_off + p * 16 * ROWB + ko);
#pragma unroll
            for (int mt = 0; mt < 2; mt++) {
#pragma unroll
                for (int nt = 0; nt < 8; nt++) {
                    const int p = nt >> 1, h = (nt & 1) * 2;
                    mma_f16(acc[mt][nt], ah[mt], bh[p][h], bh[p][h + 1]);
                }
            }
        }
        __syncthreads();
        st = (st + 1) % STAGES;
    }

    // epilogue: fp16 store
#pragma unroll
    for (int mt = 0; mt < 2; mt++) {
#pragma unroll
        for (int nt = 0; nt < 8; nt++) {
            int r = warp_m * 32 + mt * 16 + (lane >> 2);
            int c = warp_n * 64 + nt * 8 + (lane & 3) * 2;
            size_t b0 = ((size_t)xi * COUT + co0 + c) * MTOT + m0;
            g_M[b0 + r] = __float2half(acc[mt][nt][0]);
            g_M[b0 + MTOT + r] = __float2half(acc[mt][nt][1]);
            g_M[b0 + r + 8] = __float2half(acc[mt][nt][2]);
            g_M[b0 + MTOT + r + 8] = __float2half(acc[mt][nt][3]);
        }
    }
}

// ---------------------------------------------------------------------------
// Y = A^T M A, * demod, scatter to NCHW.  grid = (COUT, N_), block = 256.
__global__ void k_ytrans(float* __restrict__ out) {
    extern __shared__ __align__(16) __half sm[];   // [16][1024]
    const int co = blockIdx.x, n = blockIdx.y;
    const int t = threadIdx.x;

#pragma unroll
    for (int u = 0; u < 8; u++) {
        int id = u * 256 + t;
        int xi = id >> 7, h8 = id & 127;
        ((uint4*)sm)[id] = *(const uint4*)
            &g_M[((size_t)xi * COUT + co) * MTOT + (size_t)n * 1024 + h8 * 8];
    }
    __syncthreads();

    const float dm = g_dm[n * COUT + co];
#pragma unroll
    for (int p = 0; p < 4; p++) {
        int tile = p * 256 + t;
        int ty = tile >> 5, tx = tile & 31;
        float m[4][4];
#pragma unroll
        for (int xi = 0; xi < 16; xi++)
            m[xi >> 2][xi & 3] = __half2float(sm[xi * 1024 + tile]);
        float z[2][4];
#pragma unroll
        for (int c = 0; c < 4; c++) {
            z[0][c] = m[0][c] + m[1][c] + m[2][c];
            z[1][c] = m[1][c] - m[2][c] - m[3][c];
        }
        size_t ob = (((size_t)(n * COUT + co)) * HH + 2 * ty) * WW + 2 * tx;
        float2 r0 = make_float2((z[0][0] + z[0][1] + z[0][2]) * dm,
                                (z[0][1] - z[0][2] - z[0][3]) * dm);
        float2 r1 = make_float2((z[1][0] + z[1][1] + z[1][2]) * dm,
                                (z[1][1] - z[1][2] - z[1][3]) * dm);
        *(float2*)&out[ob] = r0;
        *(float2*)&out[ob + WW] = r1;
    }
}

// ---------------------------------------------------------------------------
extern "C" void kernel_launch(void* const* d_in, const int* in_sizes, int n_in,
                              void* d_out, int out_size) {
    const float* x       = (const float*)d_in[0];   // [16,512,64,64]
    const float* style   = (const float*)d_in[1];   // [16,512]
    const float* weight  = (const float*)d_in[2];   // [512,512,3,3]
    const float* style_w = (const float*)d_in[3];   // [512,512]
    const float* style_b = (const float*)d_in[4];   // [512]
    float* out = (float*)d_out;                     // [16,512,64,64]

    k_wprep<<<COUT, 256>>>(weight);
    dim3 sg(N_, 16);
    k_style<<<sg, 256>>>(style, style_w, style_b);
    k_demod<<<sg, 256>>>();
    dim3 vg(16, N_, 32 / VSTRIP);
    k_vtrans<<<vg, 256>>>(x);

    cudaFuncSetAttribute(k_gemm, cudaFuncAttributeMaxDynamicSharedMemorySize, SMEM_TOTAL);
    dim3 gg(MTOT / TILE_M, COUT / TILE_N, 16);      // (128, 4, 16)
    k_gemm<<<gg, 256, SMEM_TOTAL>>>();

    cudaFuncSetAttribute(k_ytrans, cudaFuncAttributeMaxDynamicSharedMemorySize, 32768);
    dim3 yg(COUT, N_);
    k_ytrans<<<yg, 256, 32768>>>(out);
}

// round 15
// speedup vs baseline: 1.0325x; 1.0325x over previous
#include <cuda_runtime.h>
#include <cuda_fp16.h>
#include <cstdint>

// ---------------- problem constants ----------------
#define N_    16
#define CIN   512
#define COUT  512
#define HH    64
#define WW    64
#define SDIM  512
#define EPSF  1e-8f
#define MTOT  (N_ * 32 * 32)       // 16384 winograd tiles

// ---------------- GEMM tiling ----------------
#define TILE_M 128
#define TILE_N 128
#define KCH    32                  // ci per k-chunk
#define NITER  (CIN / KCH)         // 16
#define STAGES 3
#define ROWB   80                  // padded smem row stride (bytes) for 64B rows
#define ARR_B  (128 * ROWB)
#define STAGE_B (2 * ARR_B)
#define SMEM_TOTAL (STAGES * STAGE_B)   // 61440

#define VSTRIP 8                   // vtrans strip length (R12 optimum)

// ---------------- device scratch ----------------
__device__ float g_s[N_ * CIN];
__device__ float g_wsq[COUT * CIN];
__device__ float g_dm[N_ * COUT];
__device__ __half g_U[(size_t)16 * COUT * CIN];     // weight transform, [xi][co][ci]
__device__ __half g_V[(size_t)16 * MTOT * CIN];     // input transform,  [xi][m][ci]
__device__ __half g_M[(size_t)16 * COUT * MTOT];    // GEMM result fp16, [xi][co][m]

// ---------------- PTX helpers ----------------
__device__ __forceinline__ uint32_t smem_u32(const void* p) {
    uint32_t a;
    asm("{ .reg .u64 t; cvta.to.shared.u64 t, %1; cvt.u32.u64 %0, t; }" : "=r"(a) : "l"(p));
    return a;
}
__device__ __forceinline__ void cp16(uint32_t dst, const void* src) {
    asm volatile("cp.async.cg.shared.global [%0], [%1], 16;" :: "r"(dst), "l"(src));
}
#define CP_COMMIT() asm volatile("cp.async.commit_group;" ::: "memory")
#define CP_WAIT2()  asm volatile("cp.async.wait_group 2;" ::: "memory")

__device__ __forceinline__ void ldm_x4(uint32_t r[4], uint32_t addr) {
    asm volatile("ldmatrix.sync.aligned.m8n8.x4.shared.b16 {%0,%1,%2,%3}, [%4];"
                 : "=r"(r[0]), "=r"(r[1]), "=r"(r[2]), "=r"(r[3]) : "r"(addr));
}
__device__ __forceinline__ void mma_f16(float c[4], const uint32_t a[4],
                                        uint32_t b0, uint32_t b1) {
    asm volatile(
        "mma.sync.aligned.m16n8k16.row.col.f32.f16.f16.f32 "
        "{%0,%1,%2,%3}, {%4,%5,%6,%7}, {%8,%9}, {%0,%1,%2,%3};"
        : "+f"(c[0]), "+f"(c[1]), "+f"(c[2]), "+f"(c[3])
        : "r"(a[0]), "r"(a[1]), "r"(a[2]), "r"(a[3]), "r"(b0), "r"(b1));
}
__device__ __forceinline__ float warp_sum(float v) {
#pragma unroll
    for (int o = 16; o > 0; o >>= 1)
        v += __shfl_xor_sync(0xFFFFFFFFu, v, o);
    return v;
}
__device__ __forceinline__ float4 f4add(float4 a, float4 b) {
    return make_float4(a.x + b.x, a.y + b.y, a.z + b.z, a.w + b.w);
}
__device__ __forceinline__ float4 f4sub(float4 a, float4 b) {
    return make_float4(a.x - b.x, a.y - b.y, a.z - b.z, a.w - b.w);
}

// ---------------------------------------------------------------------------
// U = G (w*ws) G^T  fp16 [xi][co][ci]; also wsq.  Coalesced via smem staging.
__global__ void k_wprep(const float* __restrict__ w) {
    __shared__ float wsm[CIN * 9];   // 18 KB
    const int co = blockIdx.x, t = threadIdx.x;
    const float4* src4 = (const float4*)(w + (size_t)co * CIN * 9);
#pragma unroll
    for (int i = t; i < CIN * 9 / 4; i += 256) ((float4*)wsm)[i] = src4[i];
    __syncthreads();
    const float ws = rsqrtf((float)(CIN * 9));
#pragma unroll
    for (int cq = 0; cq < 2; cq++) {
        int ci = cq * 256 + t;
        float g[9], acc = 0.f;
#pragma unroll
        for (int i = 0; i < 9; i++) { g[i] = wsm[ci * 9 + i]; acc += g[i] * g[i]; }
        g_wsq[co * CIN + ci] = acc;
#pragma unroll
        for (int i = 0; i < 9; i++) g[i] *= ws;
        float tG[4][3];
#pragma unroll
        for (int c = 0; c < 3; c++) {
            tG[0][c] = g[c];
            tG[1][c] = 0.5f * (g[c] + g[3 + c] + g[6 + c]);
            tG[2][c] = 0.5f * (g[c] - g[3 + c] + g[6 + c]);
            tG[3][c] = g[6 + c];
        }
#pragma unroll
        for (int r = 0; r < 4; r++) {
            float u0 = tG[r][0];
            float u1 = 0.5f * (tG[r][0] + tG[r][1] + tG[r][2]);
            float u2 = 0.5f * (tG[r][0] - tG[r][1] + tG[r][2]);
            float u3 = tG[r][2];
            g_U[((size_t)(r * 4 + 0) * COUT + co) * CIN + ci] = __float2half(u0);
            g_U[((size_t)(r * 4 + 1) * COUT + co) * CIN + ci] = __float2half(u1);
            g_U[((size_t)(r * 4 + 2) * COUT + co) * CIN + ci] = __float2half(u2);
            g_U[((size_t)(r * 4 + 3) * COUT + co) * CIN + ci] = __float2half(u3);
        }
    }
}

// ---------------------------------------------------------------------------
__global__ void k_style(const float* __restrict__ style,
                        const float* __restrict__ style_w,
                        const float* __restrict__ style_b) {
    __shared__ float sty[SDIM];
    const int n = blockIdx.x;
    const int t = threadIdx.x, lane = t & 31, wp = t >> 5;
    sty[t] = style[n * SDIM + t];
    sty[t + 256] = style[n * SDIM + t + 256];
    __syncthreads();
    const float lin_scale = rsqrtf((float)SDIM);
#pragma unroll
    for (int q = 0; q < 4; q++) {
        int c = blockIdx.y * 32 + wp * 4 + q;
        const float* wr = style_w + (size_t)c * SDIM;
        float acc = 0.f;
#pragma unroll
        for (int i = 0; i < SDIM / 32; i++)
            acc += sty[i * 32 + lane] * wr[i * 32 + lane];
        acc = warp_sum(acc);
        if (lane == 0) g_s[n * CIN + c] = acc * lin_scale + style_b[c];
    }
}

// ---------------------------------------------------------------------------
__global__ void k_demod() {
    __shared__ float s2[CIN];
    const int n = blockIdx.x;
    const int t = threadIdx.x, lane = t & 31, wp = t >> 5;
    float a0 = g_s[n * CIN + t], a1 = g_s[n * CIN + t + 256];
    s2[t] = a0 * a0;
    s2[t + 256] = a1 * a1;
    __syncthreads();
    const float ws = rsqrtf((float)(CIN * 9));
#pragma unroll
    for (int q = 0; q < 4; q++) {
        int o = blockIdx.y * 32 + wp * 4 + q;
        const float* wr = g_wsq + (size_t)o * CIN;
        float acc = 0.f;
#pragma unroll
        for (int i = 0; i < CIN / 32; i++)
            acc += s2[i * 32 + lane] * wr[i * 32 + lane];
        acc = warp_sum(acc);
        if (lane == 0) g_dm[n * COUT + o] = rsqrtf(ws * ws * acc + EPSF);
    }
}

// ---------------------------------------------------------------------------
// V = B^T (x*s) B  fp16 [xi][m][ci], rolling 4-row ring buffer (R12 version).
// grid = (16 cig, N_ n, 32/VSTRIP strips), block = 256
__global__ void k_vtrans(const float* __restrict__ x) {
    __shared__ float srow[4][66][36];   // ring slot = (y+1)&3; 16B-aligned float4
    __shared__ float ssc[32];
    const int cig = blockIdx.x, n = blockIdx.y;
    const int ty0 = blockIdx.z * VSTRIP;
    const int t = threadIdx.x;

    if (t < 32) ssc[t] = g_s[n * CIN + cig * 32 + t];
    {   // zero halo columns 0 and 65 in all 4 slots (256 threads exactly)
        int r = t >> 6, side = (t >> 5) & 1, ci = t & 31;
        srow[r][side * 65][ci] = 0.f;
    }
    __syncthreads();   // ssc + halo visible before any scaled fill

    const float* xb = x + ((size_t)(n * CIN + cig * 32)) * HH * WW;

    // initial fill: rows y = 2*ty0-1 .. 2*ty0+2
#pragma unroll
    for (int rr = 0; rr < 4; rr++) {
        int y = 2 * ty0 - 1 + rr;
        int slot = (y + 1) & 3;
        int xq = t & 15, ci = t >> 4;
#pragma unroll
        for (int half = 0; half < 2; half++) {
            int cih = ci + half * 16;
            float4 v = make_float4(0.f, 0.f, 0.f, 0.f);
            if (y >= 0 && y < HH)
                v = *(const float4*)&xb[((size_t)cih * HH + y) * WW + xq * 4];
            float sc = ssc[cih];
            srow[slot][xq * 4 + 1][cih] = v.x * sc;
            srow[slot][xq * 4 + 2][cih] = v.y * sc;
            srow[slot][xq * 4 + 3][cih] = v.z * sc;
            srow[slot][xq * 4 + 4][cih] = v.w * sc;
        }
    }
    __syncthreads();

    const int ttx = t >> 3;           // tile column 0..31
    const int tci = (t & 7) * 4;      // ci base within group (0..28 step 4)

    for (int ty = ty0; ty < ty0 + VSTRIP; ty++) {
        // ---- transform: 4 ci lanes as float4, one tile column per thread ----
        float4 d[4][4];
#pragma unroll
        for (int r = 0; r < 4; r++) {
            int slot = (2 * ty + r) & 3;
#pragma unroll
            for (int c = 0; c < 4; c++)
                d[r][c] = *(const float4*)&srow[slot][2 * ttx + c][tci];
        }
        float4 z[4][4];
#pragma unroll
        for (int c = 0; c < 4; c++) {
            z[0][c] = f4sub(d[0][c], d[2][c]);
            z[1][c] = f4add(d[1][c], d[2][c]);
            z[2][c] = f4sub(d[2][c], d[1][c]);
            z[3][c] = f4sub(d[1][c], d[3][c]);
        }
        size_t mb = ((size_t)(n * 1024 + ty * 32 + ttx)) * CIN + cig * 32 + tci;
#pragma unroll
        for (int i = 0; i < 4; i++) {
            float4 v[4];
            v[0] = f4sub(z[i][0], z[i][2]);
            v[1] = f4add(z[i][1], z[i][2]);
            v[2] = f4sub(z[i][2], z[i][1]);
            v[3] = f4sub(z[i][1], z[i][3]);
#pragma unroll
            for (int j = 0; j < 4; j++) {
                __half2 h0 = __floats2half2_rn(v[j].x, v[j].y);
                __half2 h1 = __floats2half2_rn(v[j].z, v[j].w);
                uint2 u = make_uint2(*(uint32_t*)&h0, *(uint32_t*)&h1);
                *(uint2*)&g_V[(size_t)(i * 4 + j) * (MTOT * CIN) + mb] = u;
            }
        }
        if (ty + 1 < ty0 + VSTRIP) {
            __syncthreads();   // transform reads done before slot overwrite
            // ---- load 2 new rows: y = 2ty+3, 2ty+4 ----
#pragma unroll
            for (int u = 0; u < 4; u++) {
                int id = u * 256 + t;
                int rr = id >> 9;
                int rem = id & 511;
                int xq = rem & 15, ci = rem >> 4;
                int y = 2 * ty + 3 + rr;
                int slot = (y + 1) & 3;
                float4 v = make_float4(0.f, 0.f, 0.f, 0.f);
                if (y < HH)
                    v = *(const float4*)&xb[((size_t)ci * HH + y) * WW + xq * 4];
                float sc = ssc[ci];
                srow[slot][xq * 4 + 1][ci] = v.x * sc;
                srow[slot][xq * 4 + 2][ci] = v.y * sc;
                srow[slot][xq * 4 + 3][ci] = v.z * sc;
                srow[slot][xq * 4 + 4][ci] = v.w * sc;
            }
            __syncthreads();
        }
    }
}

// ---------------------------------------------------------------------------
// Stage loader: A = V[xi][m0..+128][32ci], B = U[xi][co0..+128][32ci]
__device__ __forceinline__ void load_stage(uint32_t sbase, int xi, int m0, int co0,
                                           int cic, int t) {
#pragma unroll
    for (int u = 0; u < 2; u++) {
        int id = u * 256 + t;
        int row = id >> 2, seg = id & 3;
        const __half* src = g_V + ((size_t)xi * MTOT + m0 + row) * CIN + cic * KCH + seg * 8;
        cp16(sbase + row * ROWB + seg * 16, src);
    }
#pragma unroll
    for (int u = 0; u < 2; u++) {
        int id = u * 256 + t;
        int row = id >> 2, seg = id & 3;
        const __half* src = g_U + ((size_t)xi * COUT + co0 + row) * CIN + cic * KCH + seg * 8;
        cp16(sbase + ARR_B + row * ROWB + seg * 16, src);
    }
}

// ---------------------------------------------------------------------------
// Winograd-domain GEMM: M[xi][co][m] = V[xi][m][ci] * U[xi][co][ci], fp16 out.
__global__ void __launch_bounds__(256, 2)
k_gemm() {
    extern __shared__ __align__(16) char smem[];
    const uint32_t sb = smem_u32(smem);

    const int t = threadIdx.x;
    const int lane = t & 31;
    const int w = t >> 5;
    const int warp_m = w & 3;
    const int warp_n = w >> 2;
    const int m0 = blockIdx.x * TILE_M;
    const int co0 = blockIdx.y * TILE_N;
    const int xi = blockIdx.z;

    const uint32_t a_off =
        (uint32_t)((warp_m * 32 + (lane & 15)) * ROWB + (lane >> 4) * 16);
    const uint32_t b_off =
        (uint32_t)(ARR_B +
                   (warp_n * 64 + (lane & 7) + (lane >> 4) * 8) * ROWB +
                   ((lane >> 3) & 1) * 16);

    float acc[2][8][4];
#pragma unroll
    for (int mt = 0; mt < 2; mt++)
#pragma unroll
        for (int nt = 0; nt < 8; nt++)
#pragma unroll
            for (int q = 0; q < 4; q++) acc[mt][nt][q] = 0.f;

    load_stage(sb + 0 * STAGE_B, xi, m0, co0, 0, t);
    CP_COMMIT();
    load_stage(sb + 1 * STAGE_B, xi, m0, co0, 1, t);
    CP_COMMIT();

    int st = 0;
    for (int j = 0; j < NITER; j++) {
        if (j + 2 < NITER) {
            int s2 = (j + 2) % STAGES;
            load_stage(sb + s2 * STAGE_B, xi, m0, co0, j + 2, t);
        }
        CP_COMMIT();
        CP_WAIT2();
        __syncthreads();

        const uint32_t base = sb + st * STAGE_B;
#pragma unroll
        for (int ks = 0; ks < 2; ks++) {
            const uint32_t ko = ks * 32;
            uint32_t ah[2][4];
#pragma unroll
            for (int mt = 0; mt < 2; mt++)
                ldm_x4(ah[mt], base + a_off + mt * 16 * ROWB + ko);
            uint32_t bh[4][4];
#pragma unroll
            for (int p = 0; p < 4; p++)
                ldm_x4(bh[p], base + b_off + p * 16 * ROWB + ko);
#pragma unroll
            for (int mt = 0; mt < 2; mt++) {
#pragma unroll
                for (int nt = 0; nt < 8; nt++) {
                    const int p = nt >> 1, h = (nt & 1) * 2;
                    mma_f16(acc[mt][nt], ah[mt], bh[p][h], bh[p][h + 1]);
                }
            }
        }
        __syncthreads();
        st = (st + 1) % STAGES;
    }

    // epilogue: fp16 store
#pragma unroll
    for (int mt = 0; mt < 2; mt++) {
#pragma unroll
        for (int nt = 0; nt < 8; nt++) {
            int r = warp_m * 32 + mt * 16 + (lane >> 2);
            int c = warp_n * 64 + nt * 8 + (lane & 3) * 2;
            size_t b0 = ((size_t)xi * COUT + co0 + c) * MTOT + m0;
            g_M[b0 + r] = __float2half(acc[mt][nt][0]);
            g_M[b0 + MTOT + r] = __float2half(acc[mt][nt][1]);
            g_M[b0 + r + 8] = __float2half(acc[mt][nt][2]);
            g_M[b0 + MTOT + r + 8] = __float2half(acc[mt][nt][3]);
        }
    }
}

// ---------------------------------------------------------------------------
// Y = A^T M A, * demod, scatter to NCHW.  grid = (COUT, N_), block = 256.
__global__ void k_ytrans(float* __restrict__ out) {
    extern __shared__ __align__(16) __half sm[];   // [16][1024]
    const int co = blockIdx.x, n = blockIdx.y;
    const int t = threadIdx.x;

#pragma unroll
    for (int u = 0; u < 8; u++) {
        int id = u * 256 + t;
        int xi = id >> 7, h8 = id & 127;
        ((uint4*)sm)[id] = *(const uint4*)
            &g_M[((size_t)xi * COUT + co) * MTOT + (size_t)n * 1024 + h8 * 8];
    }
    __syncthreads();

    const float dm = g_dm[n * COUT + co];
#pragma unroll
    for (int p = 0; p < 4; p++) {
        int tile = p * 256 + t;
        int ty = tile >> 5, tx = tile & 31;
        float m[4][4];
#pragma unroll
        for (int xi = 0; xi < 16; xi++)
            m[xi >> 2][xi & 3] = __half2float(sm[xi * 1024 + tile]);
        float z[2][4];
#pragma unroll
        for (int c = 0; c < 4; c++) {
            z[0][c] = m[0][c] + m[1][c] + m[2][c];
            z[1][c] = m[1][c] - m[2][c] - m[3][c];
        }
        size_t ob = (((size_t)(n * COUT + co)) * HH + 2 * ty) * WW + 2 * tx;
        float2 r0 = make_float2((z[0][0] + z[0][1] + z[0][2]) * dm,
                                (z[0][1] - z[0][2] - z[0][3]) * dm);
        float2 r1 = make_float2((z[1][0] + z[1][1] + z[1][2]) * dm,
                                (z[1][1] - z[1][2] - z[1][3]) * dm);
        *(float2*)&out[ob] = r0;
        *(float2*)&out[ob + WW] = r1;
    }
}

// ---------------------------------------------------------------------------
// Stream-overlapped launch:
//   s0: style -> vtrans ---------------------\
//   s1: wprep -> demod (after style) ---------+--> gemm -> ytrans (s0)
extern "C" void kernel_launch(void* const* d_in, const int* in_sizes, int n_in,
                              void* d_out, int out_size) {
    const float* x       = (const float*)d_in[0];   // [16,512,64,64]
    const float* style   = (const float*)d_in[1];   // [16,512]
    const float* weight  = (const float*)d_in[2];   // [512,512,3,3]
    const float* style_w = (const float*)d_in[3];   // [512,512]
    const float* style_b = (const float*)d_in[4];   // [512]
    float* out = (float*)d_out;                     // [16,512,64,64]

    cudaStream_t s1;
    cudaStreamCreateWithFlags(&s1, cudaStreamNonBlocking);
    cudaEvent_t e_fork, e_style, e_join;
    cudaEventCreateWithFlags(&e_fork, cudaEventDisableTiming);
    cudaEventCreateWithFlags(&e_style, cudaEventDisableTiming);
    cudaEventCreateWithFlags(&e_join, cudaEventDisableTiming);

    // fork: s1 joins the captured graph
    cudaEventRecord(e_fork, 0);
    cudaStreamWaitEvent(s1, e_fork, 0);

    // s1: weight transform (independent of style)
    k_wprep<<<COUT, 256, 0, s1>>>(weight);

    // s0: style modulation, then input transform
    dim3 sg(N_, 16);
    k_style<<<sg, 256>>>(style, style_w, style_b);
    cudaEventRecord(e_style, 0);

    dim3 vg(16, N_, 32 / VSTRIP);
    k_vtrans<<<vg, 256>>>(x);

    // s1: demod needs style (e_style) + wprep (program order on s1)
    cudaStreamWaitEvent(s1, e_style, 0);
    k_demod<<<sg, 256, 0, s1>>>();
    cudaEventRecord(e_join, s1);

    // join: gemm needs vtrans (s0 order) + wprep/demod (e_join)
    cudaStreamWaitEvent(0, e_join, 0);

    cudaFuncSetAttribute(k_gemm, cudaFuncAttributeMaxDynamicSharedMemorySize, SMEM_TOTAL);
    dim3 gg(MTOT / TILE_M, COUT / TILE_N, 16);      // (128, 4, 16)
    k_gemm<<<gg, 256, SMEM_TOTAL>>>();

    cudaFuncSetAttribute(k_ytrans, cudaFuncAttributeMaxDynamicSharedMemorySize, 32768);
    dim3 yg(COUT, N_);
    k_ytrans<<<yg, 256, 32768>>>(out);

    cudaEventDestroy(e_fork);
    cudaEventDestroy(e_style);
    cudaEventDestroy(e_join);
    cudaStreamDestroy(s1);
}